// round 1
// baseline (speedup 1.0000x reference)
#include <cuda_runtime.h>
#include <cstdint>

#define DIMC 1024
#define NH 16
#define HD 64
#define BB 4
#define TT 2048
#define BT (BB*TT)   // 8192

// Scratch (device globals: allocation-free contract)
__device__ float g_qkv[BT * 3 * DIMC];   // 96 MB
__device__ float g_q[BT * DIMC];         // 32 MB, layout [B,H,T,D]
__device__ float g_k[BT * DIMC];
__device__ float g_v[BT * DIMC];
__device__ float g_y[BT * DIMC];         // attention out, layout [B,T,H,D] = [BT, C]

// ---------------------------------------------------------------------------
// SGEMM: C[M,N] = A[M,K] @ B[K,N], all row-major fp32.
// 128x128 block tile, BK=16, 256 threads, 8x8 per-thread interleaved (stride 16).
// ---------------------------------------------------------------------------
__global__ __launch_bounds__(256) void sgemm128(
    const float* __restrict__ A, const float* __restrict__ Bm,
    float* __restrict__ C, int M, int N, int K)
{
    __shared__ float As[16][129];   // [k][m], pad 129 kills transposed-store conflicts
    __shared__ float Bs[16][128];   // [k][n]

    const int tid = threadIdx.x;
    const int tx = tid & 15;        // n group
    const int ty = tid >> 4;        // m group
    const int m0 = blockIdx.y << 7;
    const int n0 = blockIdx.x << 7;

    float acc[8][8];
    #pragma unroll
    for (int i = 0; i < 8; i++)
        #pragma unroll
        for (int j = 0; j < 8; j++) acc[i][j] = 0.0f;

    for (int k0 = 0; k0 < K; k0 += 16) {
        #pragma unroll
        for (int r = 0; r < 8; r++) {           // A tile: 128x16
            int idx = tid + (r << 8);
            int m = idx >> 4, kk = idx & 15;
            As[kk][m] = A[(size_t)(m0 + m) * K + (k0 + kk)];
        }
        #pragma unroll
        for (int r = 0; r < 8; r++) {           // B tile: 16x128
            int idx = tid + (r << 8);
            int kk = idx >> 7, n = idx & 127;
            Bs[kk][n] = Bm[(size_t)(k0 + kk) * N + (n0 + n)];
        }
        __syncthreads();

        #pragma unroll
        for (int kk = 0; kk < 16; kk++) {
            float a[8], b[8];
            #pragma unroll
            for (int i = 0; i < 8; i++) a[i] = As[kk][ty + 16 * i];
            #pragma unroll
            for (int j = 0; j < 8; j++) b[j] = Bs[kk][tx + 16 * j];
            #pragma unroll
            for (int i = 0; i < 8; i++)
                #pragma unroll
                for (int j = 0; j < 8; j++)
                    acc[i][j] = fmaf(a[i], b[j], acc[i][j]);
        }
        __syncthreads();
    }

    #pragma unroll
    for (int i = 0; i < 8; i++) {
        size_t row = (size_t)(m0 + ty + 16 * i) * N + n0;
        #pragma unroll
        for (int j = 0; j < 8; j++)
            C[row + tx + 16 * j] = acc[i][j];
    }
}

// ---------------------------------------------------------------------------
// RoPE + split + reshape: qkv[BT,3C] -> Q,K,V [B,H,T,D]; Q pre-scaled by 1/8.
// ---------------------------------------------------------------------------
__global__ __launch_bounds__(256) void rope_split(
    const float* __restrict__ qkv,
    float* __restrict__ Q, float* __restrict__ K, float* __restrict__ V)
{
    int gid = blockIdx.x * 256 + threadIdx.x;      // over BT*DIMC = 8388608
    if (gid >= BT * DIMC) return;

    int d  = gid & 63;
    int h  = (gid >> 6) & 15;
    int bt = gid >> 10;
    int t  = bt & (TT - 1);
    int b  = bt >> 11;

    const float* row = qkv + (size_t)bt * (3 * DIMC);

    int j = d & 31;
    // inv_freq[j] = 10000^(-j/32) = exp(-j * ln(10000)/32)
    float freq = __expf(-(float)j * 0.28782313662425575f);
    float ang = (float)t * freq;
    float s, c;
    sincosf(ang, &s, &c);             // accurate range reduction (t up to 2047)

    int pair = (d < 32) ? d + 32 : d - 32;
    float sign = (d < 32) ? -1.0f : 1.0f;

    float qv = row[h * 64 + d];
    float qp = row[h * 64 + pair];
    float kv = row[DIMC + h * 64 + d];
    float kp = row[DIMC + h * 64 + pair];
    float vv = row[2 * DIMC + h * 64 + d];

    size_t o = ((size_t)(b * NH + h) * TT + t) * HD + d;
    Q[o] = (qv * c + sign * qp * s) * 0.125f;   // fold 1/sqrt(64)
    K[o] =  kv * c + sign * kp * s;
    V[o] =  vv;
}

// ---------------------------------------------------------------------------
// Flash attention (causal), fp32. 64x64 tiles, 256 threads, 4x4 interleaved.
// Q,K,V in [B,H,T,D]; output Y in [B,T,H,D] (= [BT, C] rows for proj GEMM).
// ---------------------------------------------------------------------------
#define TW 65
__global__ __launch_bounds__(256) void attn_kernel(
    const float* __restrict__ Q, const float* __restrict__ K,
    const float* __restrict__ V, float* __restrict__ Y)
{
    extern __shared__ float sm[];
    float* Qs = sm;                 // [d][q]  64 x TW
    float* Ks = sm + 64 * TW;       // [d][k]
    float* Vs = sm + 2 * 64 * TW;   // [k][d]
    float* Ps = sm + 3 * 64 * TW;   // [q][k]

    const int tid = threadIdx.x;
    const int tx = tid & 15;        // k / d group
    const int ty = tid >> 4;        // q group
    const int qb = blockIdx.x;
    const int bh = blockIdx.y;
    const int b  = bh >> 4;
    const int h  = bh & 15;

    const float* Qg = Q + ((size_t)bh * TT + qb * 64) * HD;
    const float* Kg = K + (size_t)bh * TT * HD;
    const float* Vg = V + (size_t)bh * TT * HD;

    // load Q tile transposed into shared: Qs[d][q]
    #pragma unroll
    for (int r = 0; r < 16; r++) {
        int idx = tid + (r << 8);
        int q = idx >> 6, d = idx & 63;
        Qs[d * TW + q] = Qg[q * 64 + d];
    }

    float m[4], l[4], acc[4][4];
    #pragma unroll
    for (int i = 0; i < 4; i++) {
        m[i] = -1e30f; l[i] = 0.0f;
        #pragma unroll
        for (int j = 0; j < 4; j++) acc[i][j] = 0.0f;
    }

    for (int kb = 0; kb <= qb; kb++) {
        __syncthreads();   // protect Ks/Vs from previous iteration's readers
        #pragma unroll
        for (int r = 0; r < 16; r++) {
            int idx = tid + (r << 8);
            int k = idx >> 6, d = idx & 63;
            Ks[d * TW + k] = Kg[(size_t)(kb * 64 + k) * 64 + d];
            Vs[k * TW + d] = Vg[(size_t)(kb * 64 + k) * 64 + d];
        }
        __syncthreads();

        // S = Q @ K^T (Q already scaled)
        float s[4][4];
        #pragma unroll
        for (int i = 0; i < 4; i++)
            #pragma unroll
            for (int j = 0; j < 4; j++) s[i][j] = 0.0f;

        #pragma unroll 8
        for (int d = 0; d < 64; d++) {
            float qv[4], kv[4];
            #pragma unroll
            for (int i = 0; i < 4; i++) qv[i] = Qs[d * TW + ty + 16 * i];
            #pragma unroll
            for (int j = 0; j < 4; j++) kv[j] = Ks[d * TW + tx + 16 * j];
            #pragma unroll
            for (int i = 0; i < 4; i++)
                #pragma unroll
                for (int j = 0; j < 4; j++)
                    s[i][j] = fmaf(qv[i], kv[j], s[i][j]);
        }

        if (kb == qb) {   // causal mask on diagonal block
            #pragma unroll
            for (int i = 0; i < 4; i++)
                #pragma unroll
                for (int j = 0; j < 4; j++)
                    if ((tx + 16 * j) > (ty + 16 * i)) s[i][j] = -1e30f;
        }

        // online softmax (per-row stats, 16-lane shuffle reductions)
        #pragma unroll
        for (int i = 0; i < 4; i++) {
            float mloc = s[i][0];
            #pragma unroll
            for (int j = 1; j < 4; j++) mloc = fmaxf(mloc, s[i][j]);
            #pragma unroll
            for (int off = 8; off > 0; off >>= 1)
                mloc = fmaxf(mloc, __shfl_xor_sync(0xffffffffu, mloc, off, 16));
            float mnew = fmaxf(m[i], mloc);
            float alpha = __expf(m[i] - mnew);
            m[i] = mnew;
            float rs = 0.0f;
            #pragma unroll
            for (int j = 0; j < 4; j++) {
                s[i][j] = __expf(s[i][j] - mnew);
                rs += s[i][j];
            }
            #pragma unroll
            for (int off = 8; off > 0; off >>= 1)
                rs += __shfl_xor_sync(0xffffffffu, rs, off, 16);
            l[i] = l[i] * alpha + rs;
            #pragma unroll
            for (int j = 0; j < 4; j++) {
                acc[i][j] *= alpha;
                Ps[(ty + 16 * i) * TW + tx + 16 * j] = s[i][j];
            }
        }
        __syncthreads();

        // O += P @ V
        #pragma unroll 8
        for (int k = 0; k < 64; k++) {
            float pv[4], vv[4];
            #pragma unroll
            for (int i = 0; i < 4; i++) pv[i] = Ps[(ty + 16 * i) * TW + k];
            #pragma unroll
            for (int j = 0; j < 4; j++) vv[j] = Vs[k * TW + tx + 16 * j];
            #pragma unroll
            for (int i = 0; i < 4; i++)
                #pragma unroll
                for (int j = 0; j < 4; j++)
                    acc[i][j] = fmaf(pv[i], vv[j], acc[i][j]);
        }
    }

    // normalize + write Y in [B,T,H,D]
    #pragma unroll
    for (int i = 0; i < 4; i++) {
        float inv = 1.0f / l[i];
        int q = qb * 64 + ty + 16 * i;
        size_t row = ((size_t)(b * TT + q) * NH + h) * HD;
        #pragma unroll
        for (int j = 0; j < 4; j++)
            Y[row + tx + 16 * j] = acc[i][j] * inv;
    }
}

// ---------------------------------------------------------------------------
extern "C" void kernel_launch(void* const* d_in, const int* in_sizes, int n_in,
                              void* d_out, int out_size)
{
    const float* x     = (const float*)d_in[0];   // [B,T,C]
    const float* Wqkv  = (const float*)d_in[1];   // [C, 3C]
    const float* Wproj = (const float*)d_in[2];   // [C, C]
    float* out = (float*)d_out;                   // [B,T,C]

    float *qkv, *q, *k, *v, *y;
    cudaGetSymbolAddress((void**)&qkv, g_qkv);
    cudaGetSymbolAddress((void**)&q,   g_q);
    cudaGetSymbolAddress((void**)&k,   g_k);
    cudaGetSymbolAddress((void**)&v,   g_v);
    cudaGetSymbolAddress((void**)&y,   g_y);

    // 1) qkv = x @ Wqkv   (8192 x 3072 x 1024)
    sgemm128<<<dim3(3 * DIMC / 128, BT / 128), 256>>>(x, Wqkv, qkv, BT, 3 * DIMC, DIMC);

    // 2) split + RoPE (+ q scaling)
    rope_split<<<(BT * DIMC + 255) / 256, 256>>>(qkv, q, k, v);

    // 3) causal flash attention
    const int smem_bytes = 4 * 64 * TW * (int)sizeof(float);   // 66560
    cudaFuncSetAttribute(attn_kernel, cudaFuncAttributeMaxDynamicSharedMemorySize, smem_bytes);
    attn_kernel<<<dim3(TT / 64, BB * NH), 256, smem_bytes>>>(q, k, v, y);

    // 4) out = y @ Wproj  (8192 x 1024 x 1024)
    sgemm128<<<dim3(DIMC / 128, BT / 128), 256>>>(y, Wproj, out, BT, DIMC, DIMC);
}

// round 2
// speedup vs baseline: 1.7379x; 1.7379x over previous
#include <cuda_runtime.h>
#include <cstdint>

#define DIMC 1024
#define NH 16
#define HD 64
#define BB 4
#define TT 2048
#define BT (BB*TT)   // 8192

// Scratch (device globals: allocation-free contract)
__device__ float g_qkv[BT * 3 * DIMC];   // 96 MB
__device__ float g_q[BT * DIMC];         // 32 MB, layout [B,H,T,D]
__device__ float g_k[BT * DIMC];
__device__ float g_v[BT * DIMC];
__device__ float g_y[BT * DIMC];         // attention out, layout [B,T,H,D] = [BT, C]

// ---------------------------------------------------------------------------
// TF32 helpers
// ---------------------------------------------------------------------------
__device__ __forceinline__ uint32_t f2tf32(float f) {
    uint32_t u;
    asm("cvt.rna.tf32.f32 %0, %1;" : "=r"(u) : "f"(f));
    return u;
}

__device__ __forceinline__ void mma_tf32(float c[4],
    uint32_t a0, uint32_t a1, uint32_t a2, uint32_t a3,
    uint32_t b0, uint32_t b1)
{
    asm volatile(
        "mma.sync.aligned.m16n8k8.row.col.f32.tf32.tf32.f32 "
        "{%0,%1,%2,%3}, {%4,%5,%6,%7}, {%8,%9}, {%0,%1,%2,%3};"
        : "+f"(c[0]), "+f"(c[1]), "+f"(c[2]), "+f"(c[3])
        : "r"(a0), "r"(a1), "r"(a2), "r"(a3), "r"(b0), "r"(b1));
}

// ---------------------------------------------------------------------------
// TF32 GEMM: C[M,N] = A[M,K] @ B[K,N], row-major fp32 in/out.
// Block 128x128, BK=16, 256 threads (8 warps, 2m x 4n), warp tile 64x32.
// A smem [m][k] stride 20; B smem [k][n] stride 136 (both conflict-free).
// ---------------------------------------------------------------------------
#define AST 20
#define BST 136
__global__ __launch_bounds__(256) void gemm_tf32(
    const float* __restrict__ A, const float* __restrict__ Bm,
    float* __restrict__ C, int M, int N, int K)
{
    __shared__ uint32_t As[128 * AST];   // [m][k]
    __shared__ uint32_t Bs[16 * BST];    // [k][n]

    const int tid  = threadIdx.x;
    const int lane = tid & 31;
    const int warp = tid >> 5;
    const int wm = warp & 1;             // 0..1
    const int wn = warp >> 1;            // 0..3
    const int m0 = blockIdx.y << 7;
    const int n0 = blockIdx.x << 7;
    const int m0w = wm * 64;
    const int n0w = wn * 32;

    const int row = lane >> 2;           // 0..7
    const int tig = lane & 3;            // 0..3

    float acc[4][4][4];                  // [mt][nt][reg]
    #pragma unroll
    for (int i = 0; i < 4; i++)
        #pragma unroll
        for (int j = 0; j < 4; j++)
            #pragma unroll
            for (int r = 0; r < 4; r++) acc[i][j][r] = 0.0f;

    for (int k0 = 0; k0 < K; k0 += 16) {
        // load A tile 128x16 (512 float4, 2 per thread)
        #pragma unroll
        for (int it = 0; it < 2; it++) {
            int idx = tid + (it << 8);
            int ra = idx >> 2, c4 = (idx & 3) << 2;
            const float4 v = *(const float4*)&A[(size_t)(m0 + ra) * K + k0 + c4];
            uint4 u = { f2tf32(v.x), f2tf32(v.y), f2tf32(v.z), f2tf32(v.w) };
            *(uint4*)&As[ra * AST + c4] = u;
        }
        // load B tile 16x128 (512 float4, 2 per thread)
        #pragma unroll
        for (int it = 0; it < 2; it++) {
            int idx = tid + (it << 8);
            int rb = idx >> 5, c4 = (idx & 31) << 2;
            const float4 v = *(const float4*)&Bm[(size_t)(k0 + rb) * N + n0 + c4];
            uint4 u = { f2tf32(v.x), f2tf32(v.y), f2tf32(v.z), f2tf32(v.w) };
            *(uint4*)&Bs[rb * BST + c4] = u;
        }
        __syncthreads();

        #pragma unroll
        for (int kc = 0; kc < 16; kc += 8) {
            uint32_t af[4][4], bf[4][2];
            #pragma unroll
            for (int mt = 0; mt < 4; mt++) {
                int mr = m0w + mt * 16 + row;
                af[mt][0] = As[mr * AST + kc + tig];
                af[mt][1] = As[(mr + 8) * AST + kc + tig];
                af[mt][2] = As[mr * AST + kc + tig + 4];
                af[mt][3] = As[(mr + 8) * AST + kc + tig + 4];
            }
            #pragma unroll
            for (int nt = 0; nt < 4; nt++) {
                int nc = n0w + nt * 8 + row;
                bf[nt][0] = Bs[(kc + tig) * BST + nc];
                bf[nt][1] = Bs[(kc + tig + 4) * BST + nc];
            }
            #pragma unroll
            for (int mt = 0; mt < 4; mt++)
                #pragma unroll
                for (int nt = 0; nt < 4; nt++)
                    mma_tf32(acc[mt][nt], af[mt][0], af[mt][1], af[mt][2], af[mt][3],
                             bf[nt][0], bf[nt][1]);
        }
        __syncthreads();
    }

    // epilogue: c0,c1 at (row, 2*tig), c2,c3 at (row+8, 2*tig)
    #pragma unroll
    for (int mt = 0; mt < 4; mt++) {
        int mr = m0 + m0w + mt * 16 + row;
        #pragma unroll
        for (int nt = 0; nt < 4; nt++) {
            int nc = n0 + n0w + nt * 8 + 2 * tig;
            float2 lo = { acc[mt][nt][0], acc[mt][nt][1] };
            float2 hi = { acc[mt][nt][2], acc[mt][nt][3] };
            *(float2*)&C[(size_t)mr * N + nc] = lo;
            *(float2*)&C[(size_t)(mr + 8) * N + nc] = hi;
        }
    }
}

// ---------------------------------------------------------------------------
// RoPE + split + reshape: qkv[BT,3C] -> Q,K,V [B,H,T,D]; Q pre-scaled by 1/8.
// ---------------------------------------------------------------------------
__global__ __launch_bounds__(256) void rope_split(
    const float* __restrict__ qkv,
    float* __restrict__ Q, float* __restrict__ K, float* __restrict__ V)
{
    int gid = blockIdx.x * 256 + threadIdx.x;      // over BT*DIMC = 8388608
    if (gid >= BT * DIMC) return;

    int d  = gid & 63;
    int h  = (gid >> 6) & 15;
    int bt = gid >> 10;
    int t  = bt & (TT - 1);
    int b  = bt >> 11;

    const float* row = qkv + (size_t)bt * (3 * DIMC);

    int j = d & 31;
    float freq = __expf(-(float)j * 0.28782313662425575f);
    float ang = (float)t * freq;
    float s, c;
    sincosf(ang, &s, &c);

    int pair = (d < 32) ? d + 32 : d - 32;
    float sign = (d < 32) ? -1.0f : 1.0f;

    float qv = row[h * 64 + d];
    float qp = row[h * 64 + pair];
    float kv = row[DIMC + h * 64 + d];
    float kp = row[DIMC + h * 64 + pair];
    float vv = row[2 * DIMC + h * 64 + d];

    size_t o = ((size_t)(b * NH + h) * TT + t) * HD + d;
    Q[o] = (qv * c + sign * qp * s) * 0.125f;   // fold 1/sqrt(64)
    K[o] =  kv * c + sign * kp * s;
    V[o] =  vv;
}

// ---------------------------------------------------------------------------
// Flash attention (causal), fp32. 64x64 tiles, 256 threads, 4x4 interleaved.
// Q,K,V in [B,H,T,D]; output Y in [B,T,H,D] (= [BT, C] rows for proj GEMM).
// ---------------------------------------------------------------------------
#define TW 65
__global__ __launch_bounds__(256) void attn_kernel(
    const float* __restrict__ Q, const float* __restrict__ K,
    const float* __restrict__ V, float* __restrict__ Y)
{
    extern __shared__ float sm[];
    float* Qs = sm;                 // [d][q]  64 x TW
    float* Ks = sm + 64 * TW;       // [d][k]
    float* Vs = sm + 2 * 64 * TW;   // [k][d]
    float* Ps = sm + 3 * 64 * TW;   // [q][k]

    const int tid = threadIdx.x;
    const int tx = tid & 15;        // k / d group
    const int ty = tid >> 4;        // q group
    const int qb = blockIdx.x;
    const int bh = blockIdx.y;
    const int b  = bh >> 4;
    const int h  = bh & 15;

    const float* Qg = Q + ((size_t)bh * TT + qb * 64) * HD;
    const float* Kg = K + (size_t)bh * TT * HD;
    const float* Vg = V + (size_t)bh * TT * HD;

    #pragma unroll
    for (int r = 0; r < 16; r++) {
        int idx = tid + (r << 8);
        int q = idx >> 6, d = idx & 63;
        Qs[d * TW + q] = Qg[q * 64 + d];
    }

    float m[4], l[4], acc[4][4];
    #pragma unroll
    for (int i = 0; i < 4; i++) {
        m[i] = -1e30f; l[i] = 0.0f;
        #pragma unroll
        for (int j = 0; j < 4; j++) acc[i][j] = 0.0f;
    }

    for (int kb = 0; kb <= qb; kb++) {
        __syncthreads();
        #pragma unroll
        for (int r = 0; r < 16; r++) {
            int idx = tid + (r << 8);
            int k = idx >> 6, d = idx & 63;
            Ks[d * TW + k] = Kg[(size_t)(kb * 64 + k) * 64 + d];
            Vs[k * TW + d] = Vg[(size_t)(kb * 64 + k) * 64 + d];
        }
        __syncthreads();

        float s[4][4];
        #pragma unroll
        for (int i = 0; i < 4; i++)
            #pragma unroll
            for (int j = 0; j < 4; j++) s[i][j] = 0.0f;

        #pragma unroll 8
        for (int d = 0; d < 64; d++) {
            float qv[4], kv[4];
            #pragma unroll
            for (int i = 0; i < 4; i++) qv[i] = Qs[d * TW + ty + 16 * i];
            #pragma unroll
            for (int j = 0; j < 4; j++) kv[j] = Ks[d * TW + tx + 16 * j];
            #pragma unroll
            for (int i = 0; i < 4; i++)
                #pragma unroll
                for (int j = 0; j < 4; j++)
                    s[i][j] = fmaf(qv[i], kv[j], s[i][j]);
        }

        if (kb == qb) {
            #pragma unroll
            for (int i = 0; i < 4; i++)
                #pragma unroll
                for (int j = 0; j < 4; j++)
                    if ((tx + 16 * j) > (ty + 16 * i)) s[i][j] = -1e30f;
        }

        #pragma unroll
        for (int i = 0; i < 4; i++) {
            float mloc = s[i][0];
            #pragma unroll
            for (int j = 1; j < 4; j++) mloc = fmaxf(mloc, s[i][j]);
            #pragma unroll
            for (int off = 8; off > 0; off >>= 1)
                mloc = fmaxf(mloc, __shfl_xor_sync(0xffffffffu, mloc, off, 16));
            float mnew = fmaxf(m[i], mloc);
            float alpha = __expf(m[i] - mnew);
            m[i] = mnew;
            float rs = 0.0f;
            #pragma unroll
            for (int j = 0; j < 4; j++) {
                s[i][j] = __expf(s[i][j] - mnew);
                rs += s[i][j];
            }
            #pragma unroll
            for (int off = 8; off > 0; off >>= 1)
                rs += __shfl_xor_sync(0xffffffffu, rs, off, 16);
            l[i] = l[i] * alpha + rs;
            #pragma unroll
            for (int j = 0; j < 4; j++) {
                acc[i][j] *= alpha;
                Ps[(ty + 16 * i) * TW + tx + 16 * j] = s[i][j];
            }
        }
        __syncthreads();

        #pragma unroll 8
        for (int k = 0; k < 64; k++) {
            float pv[4], vv[4];
            #pragma unroll
            for (int i = 0; i < 4; i++) pv[i] = Ps[(ty + 16 * i) * TW + k];
            #pragma unroll
            for (int j = 0; j < 4; j++) vv[j] = Vs[k * TW + tx + 16 * j];
            #pragma unroll
            for (int i = 0; i < 4; i++)
                #pragma unroll
                for (int j = 0; j < 4; j++)
                    acc[i][j] = fmaf(pv[i], vv[j], acc[i][j]);
        }
    }

    #pragma unroll
    for (int i = 0; i < 4; i++) {
        float inv = 1.0f / l[i];
        int q = qb * 64 + ty + 16 * i;
        size_t row = ((size_t)(b * TT + q) * NH + h) * HD;
        #pragma unroll
        for (int j = 0; j < 4; j++)
            Y[row + tx + 16 * j] = acc[i][j] * inv;
    }
}

// ---------------------------------------------------------------------------
extern "C" void kernel_launch(void* const* d_in, const int* in_sizes, int n_in,
                              void* d_out, int out_size)
{
    const float* x     = (const float*)d_in[0];   // [B,T,C]
    const float* Wqkv  = (const float*)d_in[1];   // [C, 3C]
    const float* Wproj = (const float*)d_in[2];   // [C, C]
    float* out = (float*)d_out;                   // [B,T,C]

    float *qkv, *q, *k, *v, *y;
    cudaGetSymbolAddress((void**)&qkv, g_qkv);
    cudaGetSymbolAddress((void**)&q,   g_q);
    cudaGetSymbolAddress((void**)&k,   g_k);
    cudaGetSymbolAddress((void**)&v,   g_v);
    cudaGetSymbolAddress((void**)&y,   g_y);

    // 1) qkv = x @ Wqkv   (8192 x 3072 x 1024), TF32 tensor cores
    gemm_tf32<<<dim3(3 * DIMC / 128, BT / 128), 256>>>(x, Wqkv, qkv, BT, 3 * DIMC, DIMC);

    // 2) split + RoPE (+ q scaling)
    rope_split<<<(BT * DIMC + 255) / 256, 256>>>(qkv, q, k, v);

    // 3) causal flash attention
    const int smem_bytes = 4 * 64 * TW * (int)sizeof(float);   // 66560
    cudaFuncSetAttribute(attn_kernel, cudaFuncAttributeMaxDynamicSharedMemorySize, smem_bytes);
    attn_kernel<<<dim3(TT / 64, BB * NH), 256, smem_bytes>>>(q, k, v, y);

    // 4) out = y @ Wproj  (8192 x 1024 x 1024), TF32 tensor cores
    gemm_tf32<<<dim3(DIMC / 128, BT / 128), 256>>>(y, Wproj, out, BT, DIMC, DIMC);
}

// round 4
// speedup vs baseline: 3.2185x; 1.8520x over previous
#include <cuda_runtime.h>
#include <cstdint>

#define DIMC 1024
#define NH 16
#define HD 64
#define BB 4
#define TT 2048
#define BT (BB*TT)   // 8192

// Scratch (device globals: allocation-free contract)
__device__ float g_qkv[BT * 3 * DIMC];   // 96 MB
__device__ float g_q[BT * DIMC];         // [B,H,T,D]
__device__ float g_k[BT * DIMC];
__device__ float g_v[BT * DIMC];
__device__ float g_y[BT * DIMC];         // attention out, [B,T,H,D] = [BT, C]

// ---------------------------------------------------------------------------
// TF32 helpers
// ---------------------------------------------------------------------------
__device__ __forceinline__ uint32_t f2tf32(float f) {
    uint32_t u;
    asm("cvt.rna.tf32.f32 %0, %1;" : "=r"(u) : "f"(f));
    return u;
}

__device__ __forceinline__ void mma_tf32(float c[4],
    uint32_t a0, uint32_t a1, uint32_t a2, uint32_t a3,
    uint32_t b0, uint32_t b1)
{
    asm volatile(
        "mma.sync.aligned.m16n8k8.row.col.f32.tf32.tf32.f32 "
        "{%0,%1,%2,%3}, {%4,%5,%6,%7}, {%8,%9}, {%0,%1,%2,%3};"
        : "+f"(c[0]), "+f"(c[1]), "+f"(c[2]), "+f"(c[3])
        : "r"(a0), "r"(a1), "r"(a2), "r"(a3), "r"(b0), "r"(b1));
}

// ---------------------------------------------------------------------------
// TF32 GEMM: C[M,N] = A[M,K] @ B[K,N], row-major fp32 in/out. (unchanged)
// ---------------------------------------------------------------------------
#define AST 20
#define BST 136
__global__ __launch_bounds__(256) void gemm_tf32(
    const float* __restrict__ A, const float* __restrict__ Bm,
    float* __restrict__ C, int M, int N, int K)
{
    __shared__ uint32_t As[128 * AST];
    __shared__ uint32_t Bs[16 * BST];

    const int tid  = threadIdx.x;
    const int lane = tid & 31;
    const int warp = tid >> 5;
    const int wm = warp & 1;
    const int wn = warp >> 1;
    const int m0 = blockIdx.y << 7;
    const int n0 = blockIdx.x << 7;
    const int m0w = wm * 64;
    const int n0w = wn * 32;

    const int row = lane >> 2;
    const int tig = lane & 3;

    float acc[4][4][4];
    #pragma unroll
    for (int i = 0; i < 4; i++)
        #pragma unroll
        for (int j = 0; j < 4; j++)
            #pragma unroll
            for (int r = 0; r < 4; r++) acc[i][j][r] = 0.0f;

    for (int k0 = 0; k0 < K; k0 += 16) {
        #pragma unroll
        for (int it = 0; it < 2; it++) {
            int idx = tid + (it << 8);
            int ra = idx >> 2, c4 = (idx & 3) << 2;
            const float4 v = *(const float4*)&A[(size_t)(m0 + ra) * K + k0 + c4];
            uint4 u = { f2tf32(v.x), f2tf32(v.y), f2tf32(v.z), f2tf32(v.w) };
            *(uint4*)&As[ra * AST + c4] = u;
        }
        #pragma unroll
        for (int it = 0; it < 2; it++) {
            int idx = tid + (it << 8);
            int rb = idx >> 5, c4 = (idx & 31) << 2;
            const float4 v = *(const float4*)&Bm[(size_t)(k0 + rb) * N + n0 + c4];
            uint4 u = { f2tf32(v.x), f2tf32(v.y), f2tf32(v.z), f2tf32(v.w) };
            *(uint4*)&Bs[rb * BST + c4] = u;
        }
        __syncthreads();

        #pragma unroll
        for (int kc = 0; kc < 16; kc += 8) {
            uint32_t af[4][4], bf[4][2];
            #pragma unroll
            for (int mt = 0; mt < 4; mt++) {
                int mr = m0w + mt * 16 + row;
                af[mt][0] = As[mr * AST + kc + tig];
                af[mt][1] = As[(mr + 8) * AST + kc + tig];
                af[mt][2] = As[mr * AST + kc + tig + 4];
                af[mt][3] = As[(mr + 8) * AST + kc + tig + 4];
            }
            #pragma unroll
            for (int nt = 0; nt < 4; nt++) {
                int nc = n0w + nt * 8 + row;
                bf[nt][0] = Bs[(kc + tig) * BST + nc];
                bf[nt][1] = Bs[(kc + tig + 4) * BST + nc];
            }
            #pragma unroll
            for (int mt = 0; mt < 4; mt++)
                #pragma unroll
                for (int nt = 0; nt < 4; nt++)
                    mma_tf32(acc[mt][nt], af[mt][0], af[mt][1], af[mt][2], af[mt][3],
                             bf[nt][0], bf[nt][1]);
        }
        __syncthreads();
    }

    #pragma unroll
    for (int mt = 0; mt < 4; mt++) {
        int mr = m0 + m0w + mt * 16 + row;
        #pragma unroll
        for (int nt = 0; nt < 4; nt++) {
            int nc = n0 + n0w + nt * 8 + 2 * tig;
            float2 lo = { acc[mt][nt][0], acc[mt][nt][1] };
            float2 hi = { acc[mt][nt][2], acc[mt][nt][3] };
            *(float2*)&C[(size_t)mr * N + nc] = lo;
            *(float2*)&C[(size_t)(mr + 8) * N + nc] = hi;
        }
    }
}

// ---------------------------------------------------------------------------
// RoPE + split + reshape (unchanged)
// ---------------------------------------------------------------------------
__global__ __launch_bounds__(256) void rope_split(
    const float* __restrict__ qkv,
    float* __restrict__ Q, float* __restrict__ K, float* __restrict__ V)
{
    int gid = blockIdx.x * 256 + threadIdx.x;
    if (gid >= BT * DIMC) return;

    int d  = gid & 63;
    int h  = (gid >> 6) & 15;
    int bt = gid >> 10;
    int t  = bt & (TT - 1);
    int b  = bt >> 11;

    const float* row = qkv + (size_t)bt * (3 * DIMC);

    int j = d & 31;
    float freq = __expf(-(float)j * 0.28782313662425575f);
    float ang = (float)t * freq;
    float s, c;
    sincosf(ang, &s, &c);

    int pair = (d < 32) ? d + 32 : d - 32;
    float sign = (d < 32) ? -1.0f : 1.0f;

    float qv = row[h * 64 + d];
    float qp = row[h * 64 + pair];
    float kv = row[DIMC + h * 64 + d];
    float kp = row[DIMC + h * 64 + pair];
    float vv = row[2 * DIMC + h * 64 + d];

    size_t o = ((size_t)(b * NH + h) * TT + t) * HD + d;
    Q[o] = (qv * c + sign * qp * s) * 0.125f;
    K[o] =  kv * c + sign * kp * s;
    V[o] =  vv;
}

// ---------------------------------------------------------------------------
// Tensor-core flash attention (causal). 64x64 tiles, 128 threads (4 warps).
// Each warp owns 16 full query rows (m16 x n64) -> softmax is warp-local.
// Q fragments (tf32 hi + residual) live in registers (loop-invariant).
// K smem stride 68, V/P stride 72 -> all LDS/STS patterns conflict-free.
// ---------------------------------------------------------------------------
#define KST 68
#define VST 72
#define PST 72
__global__ __launch_bounds__(128) void attn_tc(
    const float* __restrict__ Q, const float* __restrict__ K,
    const float* __restrict__ V, float* __restrict__ Y)
{
    extern __shared__ uint32_t smw[];
    uint32_t* Ks = smw;                // [kseq][d]  64 x KST
    uint32_t* Vs = Ks + 64 * KST;      // [kseq][d]  64 x VST
    uint32_t* Ps = Vs + 64 * VST;      // [q][kseq]  64 x PST

    const int tid  = threadIdx.x;
    const int lane = tid & 31;
    const int warp = tid >> 5;         // 0..3
    const int row  = lane >> 2;        // 0..7
    const int tig  = lane & 3;         // 0..3
    const int qb = blockIdx.x;
    const int bh = blockIdx.y;
    const int b  = bh >> 4;
    const int h  = bh & 15;
    const int r0 = warp * 16 + row;    // first owned row (r0 and r0+8)

    const float* Qg = Q + ((size_t)bh * TT + qb * 64) * HD;
    const float* Kg = K + (size_t)bh * TT * HD;
    const float* Vg = V + (size_t)bh * TT * HD;

    // Q fragments in registers: hi + residual, 8 k-steps x 4 regs each
    uint32_t qh[8][4], qr[8][4];
    #pragma unroll
    for (int s = 0; s < 8; s++) {
        float f0 = Qg[r0 * 64 + 8 * s + tig];
        float f1 = Qg[(r0 + 8) * 64 + 8 * s + tig];
        float f2 = Qg[r0 * 64 + 8 * s + tig + 4];
        float f3 = Qg[(r0 + 8) * 64 + 8 * s + tig + 4];
        qh[s][0] = f2tf32(f0); qr[s][0] = f2tf32(f0 - __uint_as_float(qh[s][0]));
        qh[s][1] = f2tf32(f1); qr[s][1] = f2tf32(f1 - __uint_as_float(qh[s][1]));
        qh[s][2] = f2tf32(f2); qr[s][2] = f2tf32(f2 - __uint_as_float(qh[s][2]));
        qh[s][3] = f2tf32(f3); qr[s][3] = f2tf32(f3 - __uint_as_float(qh[s][3]));
    }

    float m_[2] = { -1e30f, -1e30f };
    float l_[2] = { 0.0f, 0.0f };
    float oacc[8][4];
    #pragma unroll
    for (int nt = 0; nt < 8; nt++)
        #pragma unroll
        for (int r = 0; r < 4; r++) oacc[nt][r] = 0.0f;

    for (int kb = 0; kb <= qb; kb++) {
        __syncthreads();   // all warps done reading Ks/Vs from previous iter
        #pragma unroll
        for (int it = 0; it < 8; it++) {
            int idx = tid + it * 128;
            int k  = idx >> 4;
            int d0 = (idx & 15) << 2;
            float4 kv = *(const float4*)&Kg[(size_t)(kb * 64 + k) * 64 + d0];
            float4 vv = *(const float4*)&Vg[(size_t)(kb * 64 + k) * 64 + d0];
            uint4 ku = { f2tf32(kv.x), f2tf32(kv.y), f2tf32(kv.z), f2tf32(kv.w) };
            uint4 vu = { f2tf32(vv.x), f2tf32(vv.y), f2tf32(vv.z), f2tf32(vv.w) };
            *(uint4*)&Ks[k * KST + d0] = ku;
            *(uint4*)&Vs[k * VST + d0] = vu;
        }
        __syncthreads();

        // S = Q @ K^T (split-Q: 2 MMAs per tile)
        float sacc[8][4];
        #pragma unroll
        for (int nt = 0; nt < 8; nt++)
            #pragma unroll
            for (int r = 0; r < 4; r++) sacc[nt][r] = 0.0f;

        #pragma unroll
        for (int s = 0; s < 8; s++) {
            int kc = 8 * s;
            #pragma unroll
            for (int nt = 0; nt < 8; nt++) {
                int nc = nt * 8 + row;
                uint32_t b0 = Ks[nc * KST + kc + tig];
                uint32_t b1 = Ks[nc * KST + kc + tig + 4];
                mma_tf32(sacc[nt], qh[s][0], qh[s][1], qh[s][2], qh[s][3], b0, b1);
                mma_tf32(sacc[nt], qr[s][0], qr[s][1], qr[s][2], qr[s][3], b0, b1);
            }
        }

        if (kb == qb) {   // causal mask on diagonal block
            #pragma unroll
            for (int nt = 0; nt < 8; nt++)
                #pragma unroll
                for (int r = 0; r < 4; r++) {
                    int ql = r0 + 8 * (r >> 1);
                    int kl = nt * 8 + 2 * tig + (r & 1);
                    if (kl > ql) sacc[nt][r] = -1e30f;
                }
        }

        // warp-local online softmax (full 64-col rows within this warp)
        #pragma unroll
        for (int hh = 0; hh < 2; hh++) {
            float mx = -1e30f;
            #pragma unroll
            for (int nt = 0; nt < 8; nt++)
                mx = fmaxf(mx, fmaxf(sacc[nt][2 * hh], sacc[nt][2 * hh + 1]));
            mx = fmaxf(mx, __shfl_xor_sync(0xffffffffu, mx, 1));
            mx = fmaxf(mx, __shfl_xor_sync(0xffffffffu, mx, 2));
            float mnew = fmaxf(m_[hh], mx);
            float alpha = __expf(m_[hh] - mnew);
            m_[hh] = mnew;
            float rs = 0.0f;
            int qrow = r0 + 8 * hh;
            #pragma unroll
            for (int nt = 0; nt < 8; nt++) {
                float p0 = __expf(sacc[nt][2 * hh] - mnew);
                float p1 = __expf(sacc[nt][2 * hh + 1] - mnew);
                rs += p0 + p1;
                uint2 pu = { f2tf32(p0), f2tf32(p1) };
                *(uint2*)&Ps[qrow * PST + nt * 8 + 2 * tig] = pu;
                oacc[nt][2 * hh]     *= alpha;
                oacc[nt][2 * hh + 1] *= alpha;
            }
            rs += __shfl_xor_sync(0xffffffffu, rs, 1);
            rs += __shfl_xor_sync(0xffffffffu, rs, 2);
            l_[hh] = l_[hh] * alpha + rs;
        }
        __syncwarp();   // Ps rows are warp-private; intra-warp visibility only

        // O += P @ V
        #pragma unroll
        for (int s = 0; s < 8; s++) {
            int kc = 8 * s;
            uint32_t a0 = Ps[r0 * PST + kc + tig];
            uint32_t a1 = Ps[(r0 + 8) * PST + kc + tig];
            uint32_t a2 = Ps[r0 * PST + kc + tig + 4];
            uint32_t a3 = Ps[(r0 + 8) * PST + kc + tig + 4];
            #pragma unroll
            for (int nt = 0; nt < 8; nt++) {
                int nc = nt * 8 + row;
                uint32_t b0 = Vs[(kc + tig) * VST + nc];
                uint32_t b1 = Vs[(kc + tig + 4) * VST + nc];
                mma_tf32(oacc[nt], a0, a1, a2, a3, b0, b1);
            }
        }
    }

    // epilogue: normalize, write Y[B,T,H,D]
    #pragma unroll
    for (int hh = 0; hh < 2; hh++) {
        float inv = 1.0f / l_[hh];
        int qg = qb * 64 + r0 + 8 * hh;
        size_t base = ((size_t)(b * TT + qg) * NH + h) * HD;
        #pragma unroll
        for (int nt = 0; nt < 8; nt++) {
            int d = nt * 8 + 2 * tig;
            float2 o2 = { oacc[nt][2 * hh] * inv, oacc[nt][2 * hh + 1] * inv };
            *(float2*)&Y[base + d] = o2;
        }
    }
}

// ---------------------------------------------------------------------------
extern "C" void kernel_launch(void* const* d_in, const int* in_sizes, int n_in,
                              void* d_out, int out_size)
{
    const float* x     = (const float*)d_in[0];   // [B,T,C]
    const float* Wqkv  = (const float*)d_in[1];   // [C, 3C]
    const float* Wproj = (const float*)d_in[2];   // [C, C]
    float* out = (float*)d_out;                   // [B,T,C]

    float *qkv, *q, *k, *v, *y;
    cudaGetSymbolAddress((void**)&qkv, g_qkv);
    cudaGetSymbolAddress((void**)&q,   g_q);
    cudaGetSymbolAddress((void**)&k,   g_k);
    cudaGetSymbolAddress((void**)&v,   g_v);
    cudaGetSymbolAddress((void**)&y,   g_y);

    // 1) qkv = x @ Wqkv   (8192 x 3072 x 1024)
    gemm_tf32<<<dim3(3 * DIMC / 128, BT / 128), 256>>>(x, Wqkv, qkv, BT, 3 * DIMC, DIMC);

    // 2) split + RoPE (+ q scaling)
    rope_split<<<(BT * DIMC + 255) / 256, 256>>>(qkv, q, k, v);

    // 3) causal flash attention (tensor cores, warp-owns-rows layout)
    const int smem_bytes = 64 * (KST + VST + PST) * (int)sizeof(uint32_t);  // 54272
    cudaFuncSetAttribute(attn_tc, cudaFuncAttributeMaxDynamicSharedMemorySize, smem_bytes);
    attn_tc<<<dim3(TT / 64, BB * NH), 128, smem_bytes>>>(q, k, v, y);

    // 4) out = y @ Wproj  (8192 x 1024 x 1024)
    gemm_tf32<<<dim3(DIMC / 128, BT / 128), 256>>>(y, Wproj, out, BT, DIMC, DIMC);
}